// round 13
// baseline (speedup 1.0000x reference)
#include <cuda_runtime.h>
#include <cuda_fp16.h>
#include <cstdint>

#define TOK   2048
#define HID   2880
#define INTER 2880
#define NEXP  8
#define TOPK  4
#define N1    (2*INTER)        // 5760
#define MAXR  (NEXP*TOK)       // 16384
#define KDIM  2880

__device__ __constant__ float c_alpha = 1.702f;
__device__ __constant__ float c_limit = 7.0f;

// ---------------- static scratch ----------------
__device__ int   g_cnt[NEXP];
__device__ int   g_tok[NEXP][TOK];
__device__ int   g_pos[TOK][TOPK];
__device__ float g_w  [TOK][TOPK];
__device__ __align__(16) float  g_yp [(size_t)MAXR * HID];
__device__ __align__(16) __half g_xh [(size_t)TOK * KDIM];
__device__ __align__(16) __half g_w1h[(size_t)NEXP * KDIM * N1];   // [e][k][n]
__device__ __align__(16) __half g_w2h[(size_t)NEXP * KDIM * HID];  // [e][k][n]
__device__ __align__(16) __half g_ah [(size_t)MAXR * KDIM];

// ---------------- helpers ----------------
__device__ __forceinline__ uint32_t smem_to_u32(const void* p) {
    uint32_t a;
    asm("{ .reg .u64 t; cvta.to.shared.u64 t, %1; cvt.u32.u64 %0, t; }"
        : "=r"(a) : "l"(p));
    return a;
}
__device__ __forceinline__ void ldsm4(uint32_t* r, uint32_t addr) {
    asm volatile("ldmatrix.sync.aligned.m8n8.x4.shared.b16 {%0,%1,%2,%3}, [%4];"
                 : "=r"(r[0]), "=r"(r[1]), "=r"(r[2]), "=r"(r[3])
                 : "r"(addr) : "memory");
}
__device__ __forceinline__ void ldsm4t(uint32_t* r, uint32_t addr) {
    asm volatile("ldmatrix.sync.aligned.m8n8.x4.trans.shared.b16 {%0,%1,%2,%3}, [%4];"
                 : "=r"(r[0]), "=r"(r[1]), "=r"(r[2]), "=r"(r[3])
                 : "r"(addr) : "memory");
}
__device__ __forceinline__ void ldsm2t(uint32_t* r, uint32_t addr) {
    asm volatile("ldmatrix.sync.aligned.m8n8.x2.trans.shared.b16 {%0,%1}, [%2];"
                 : "=r"(r[0]), "=r"(r[1])
                 : "r"(addr) : "memory");
}
__device__ __forceinline__ void mma_f16(float* c, const uint32_t* a, const uint32_t* b) {
    asm volatile(
        "mma.sync.aligned.m16n8k16.row.col.f32.f16.f16.f32 "
        "{%0,%1,%2,%3}, {%4,%5,%6,%7}, {%8,%9}, {%0,%1,%2,%3};"
        : "+f"(c[0]), "+f"(c[1]), "+f"(c[2]), "+f"(c[3])
        : "r"(a[0]), "r"(a[1]), "r"(a[2]), "r"(a[3]), "r"(b[0]), "r"(b[1]));
}
__device__ __forceinline__ void cpa16(uint32_t dst, const void* src) {
    asm volatile("cp.async.cg.shared.global [%0], [%1], 16;"
                 :: "r"(dst), "l"(src) : "memory");
}
#define CP_COMMIT() asm volatile("cp.async.commit_group;" ::: "memory")
#define CP_WAIT0()  asm volatile("cp.async.wait_group 0;" ::: "memory")

union H4 { unsigned long long u; __half h[4]; };

// ---------------- router ----------------
__global__ void router_kernel(const float* __restrict__ x,
                              const float* __restrict__ gw,
                              const float* __restrict__ gb) {
    int warp = threadIdx.x >> 5, lane = threadIdx.x & 31;
    int t = blockIdx.x * 8 + warp;
    if (t >= TOK) return;
    const float* xr = x + (size_t)t * HID;
    float acc[NEXP];
#pragma unroll
    for (int e = 0; e < NEXP; e++) acc[e] = 0.f;
    for (int h = lane; h < HID; h += 32) {
        float xv = xr[h];
        const float4* g4 = reinterpret_cast<const float4*>(gw + (size_t)h * NEXP);
        float4 ga = g4[0], gbv = g4[1];
        acc[0] += xv * ga.x;  acc[1] += xv * ga.y;
        acc[2] += xv * ga.z;  acc[3] += xv * ga.w;
        acc[4] += xv * gbv.x; acc[5] += xv * gbv.y;
        acc[6] += xv * gbv.z; acc[7] += xv * gbv.w;
    }
#pragma unroll
    for (int e = 0; e < NEXP; e++)
#pragma unroll
        for (int off = 16; off; off >>= 1)
            acc[e] += __shfl_xor_sync(0xffffffffu, acc[e], off);
    if (lane == 0) {
        float lg[NEXP];
#pragma unroll
        for (int e = 0; e < NEXP; e++) lg[e] = acc[e] + gb[e];
        int idx[TOPK]; float val[TOPK]; unsigned mask = 0;
#pragma unroll
        for (int k = 0; k < TOPK; k++) {
            float best = -3.4e38f; int bi = 0;
#pragma unroll
            for (int e = 0; e < NEXP; e++)
                if (!((mask >> e) & 1u) && lg[e] > best) { best = lg[e]; bi = e; }
            mask |= 1u << bi; idx[k] = bi; val[k] = best;
        }
        float m = val[0], s = 0.f, w[TOPK];
#pragma unroll
        for (int k = 0; k < TOPK; k++) { w[k] = expf(val[k] - m); s += w[k]; }
        float inv = 1.f / s;
#pragma unroll
        for (int k = 0; k < TOPK; k++) {
            int e = idx[k];
            int p = atomicAdd(&g_cnt[e], 1);
            g_tok[e][p] = t;
            g_pos[t][k] = e * TOK + p;
            g_w[t][k]   = w[k] * inv;
        }
    }
}

// ---------------- x -> fp16 (+ zero g_cnt in block 0) ----------------
__global__ void convert_x_kernel(const float* __restrict__ x) {
    if (blockIdx.x == 0 && threadIdx.x < NEXP) g_cnt[threadIdx.x] = 0;
    size_t i4 = (size_t)blockIdx.x * blockDim.x + threadIdx.x;
    if (i4 >= (size_t)TOK * KDIM / 4) return;
    float4 v = reinterpret_cast<const float4*>(x)[i4];
    H4 h;
    h.h[0] = __float2half_rn(v.x); h.h[1] = __float2half_rn(v.y);
    h.h[2] = __float2half_rn(v.z); h.h[3] = __float2half_rn(v.w);
    reinterpret_cast<unsigned long long*>(g_xh)[i4] = h.u;
}

// ---------------- weights -> fp16, layout preserved [e][k][n] ----------------
template<int WHICH>
__global__ void convert_w_kernel(const float* __restrict__ W) {
    __half* TH = WHICH ? g_w2h : g_w1h;   // device-code symbol ref
    const size_t n4 = ((size_t)NEXP * KDIM * (WHICH ? HID : N1)) / 4;
    size_t i4 = (size_t)blockIdx.x * blockDim.x + threadIdx.x;
    if (i4 >= n4) return;
    float4 v = reinterpret_cast<const float4*>(W)[i4];
    H4 h;
    h.h[0] = __float2half_rn(v.x); h.h[1] = __float2half_rn(v.y);
    h.h[2] = __float2half_rn(v.z); h.h[3] = __float2half_rn(v.w);
    reinterpret_cast<unsigned long long*>(TH)[i4] = h.u;
}

// ---------------- clamped SwiGLU scalar ----------------
__device__ __forceinline__ float swi(float g, float l) {
    g = fminf(g, c_limit);
    l = fminf(fmaxf(l, -c_limit), c_limit);
    float s = 1.f / (1.f + expf(-c_alpha * g));
    return g * s * (l + 1.0f);
}

// ---------------- fused GEMM, CTA tile 256m x 192n, 512 threads ------------
// Warp grid 4m x 4n, warp tile 64m x 48n (f=4).
// FIRST: 96 glu + 96 lin cols; each warp owns 24 glu + matching 24 lin.
// SMEM: A [256][144B], B [64 k-rows][400B]; 2-stage cp.async.
#define KC      64
#define NCHUNK  (KDIM / KC)            // 45
#define ASTRIDE 144
#define BSTRIDE 400
#define OFF_B   36864
#define STAGE   (36864 + 25600)        // 62464
#define SMEM_GEMM (2 * STAGE + 1024)   // 125952

template<bool FIRST>
__global__ __launch_bounds__(512, 1)
void mma_gemm_kernel(const float* __restrict__ bias) {
    extern __shared__ __align__(1024) char smem[];
    int tid = threadIdx.x;
    int e = blockIdx.z;
    int ne = g_cnt[e];
    int m0 = blockIdx.x * 256;
    if (m0 >= ne) return;
    constexpr int NW = FIRST ? N1 : HID;     // B row width in gmem
    int n0 = blockIdx.y * (FIRST ? 96 : 192);

    const __half* Ah_ = FIRST ? g_xh : g_ah;
    const __half* Bh_ = FIRST ? g_w1h : g_w2h;

    int* rowid = reinterpret_cast<int*>(smem + 2 * STAGE);
    if (tid < 256) {
        int mi = m0 + tid; if (mi >= ne) mi = ne - 1;
        rowid[tid] = FIRST ? g_tok[e][mi] : (e * TOK + mi);
    }
    __syncthreads();

    uint32_t sb = smem_to_u32(smem);
    int r8  = tid >> 3;                // 0..63
    int seg = tid & 7;
    int ra[4];
#pragma unroll
    for (int j = 0; j < 4; j++) ra[j] = rowid[r8 + 64 * j];

    const __half* Be = Bh_ + (size_t)e * KDIM * NW;

    auto load_stage = [&](int stg, int chunk) {
        uint32_t sbase = sb + stg * STAGE;
        int kg0 = chunk * KC;
#pragma unroll
        for (int j = 0; j < 4; j++) {
            uint32_t so = (uint32_t)(r8 + 64 * j) * ASTRIDE + seg * 16;
            cpa16(sbase + so, Ah_ + (size_t)ra[j] * KDIM + kg0 + seg * 8);
        }
#pragma unroll
        for (int j = 0; j < 3; j++) {
            int id = tid + j * 512;             // 0..1535
            int row = id / 24, g = id - row * 24;
            int col;
            if (FIRST) col = (g < 12) ? (n0 + g * 8) : (INTER + n0 + (g - 12) * 8);
            else       col = n0 + g * 8;
            cpa16(sbase + OFF_B + (uint32_t)row * BSTRIDE + g * 16,
                  Be + (size_t)(kg0 + row) * NW + col);
        }
    };

    int w = tid >> 5, lane = tid & 31;
    int wn = w & 3, wm = w >> 2;               // 4 n-warps x 4 m-warps
    uint32_t row_add = (uint32_t)((lane & 7) + ((lane >> 3) & 1) * 8);
    uint32_t col16 = (uint32_t)(((lane >> 4) & 1) * 16);
    uint32_t bk_add = (uint32_t)((lane & 7) + ((lane >> 3) & 1) * 8);
    uint32_t bn8 = (uint32_t)((lane >> 4) * 8);

    float c[4][6][4];
#pragma unroll
    for (int f = 0; f < 4; f++)
#pragma unroll
        for (int n = 0; n < 6; n++)
#pragma unroll
            for (int k = 0; k < 4; k++) c[f][n][k] = 0.f;

    load_stage(0, 0);
    CP_COMMIT();

    for (int i = 0; i < NCHUNK; i++) {
        CP_WAIT0();
        __syncthreads();
        if (i + 1 < NCHUNK) { load_stage((i + 1) & 1, i + 1); CP_COMMIT(); }

        uint32_t st = sb + (i & 1) * STAGE;
#pragma unroll
        for (int s = 0; s < 4; s++) {
            uint32_t brow = st + OFF_B + (s * 16 + bk_add) * BSTRIDE;
            uint32_t bh[6][2];
            if (FIRST) {
                uint32_t t4[4], t2[2];
                ldsm4t(t4, brow + (uint32_t)(wn * 24) * 2 + bn8 * 2);
                bh[0][0] = t4[0]; bh[0][1] = t4[1];
                bh[1][0] = t4[2]; bh[1][1] = t4[3];
                ldsm2t(t2, brow + (uint32_t)(wn * 24 + 16) * 2);
                bh[2][0] = t2[0]; bh[2][1] = t2[1];
                ldsm4t(t4, brow + (uint32_t)(96 + wn * 24) * 2 + bn8 * 2);
                bh[3][0] = t4[0]; bh[3][1] = t4[1];
                bh[4][0] = t4[2]; bh[4][1] = t4[3];
                ldsm2t(t2, brow + (uint32_t)(96 + wn * 24 + 16) * 2);
                bh[5][0] = t2[0]; bh[5][1] = t2[1];
            } else {
#pragma unroll
                for (int q = 0; q < 3; q++) {
                    uint32_t t4[4];
                    ldsm4t(t4, brow + (uint32_t)(wn * 48 + q * 16) * 2 + bn8 * 2);
                    bh[2 * q][0] = t4[0];     bh[2 * q][1] = t4[1];
                    bh[2 * q + 1][0] = t4[2]; bh[2 * q + 1][1] = t4[3];
                }
            }
#pragma unroll
            for (int f = 0; f < 4; f++) {
                uint32_t rr = (uint32_t)(wm * 64 + f * 16) + row_add;
                uint32_t ah[4];
                ldsm4(ah, st + rr * ASTRIDE + (uint32_t)(s * 32) + col16);
#pragma unroll
                for (int n = 0; n < 6; n++)
                    mma_f16(c[f][n], ah, bh[n]);
            }
        }
    }

    int rbase = m0 + wm * 64 + (lane >> 2);
    if (FIRST) {
        const float* be = bias + (size_t)e * N1;
#pragma unroll
        for (int f = 0; f < 4; f++) {
            int r0 = rbase + f * 16;
#pragma unroll
            for (int j = 0; j < 3; j++) {
                int gc = n0 + wn * 24 + j * 8 + (lane & 3) * 2;
                float bg0 = be[gc], bg1 = be[gc + 1];
                float bl0 = be[INTER + gc], bl1 = be[INTER + gc + 1];
                if (r0 < ne) {
                    float a0 = swi(c[f][j][0] + bg0, c[f][j + 3][0] + bl0);
                    float a1 = swi(c[f][j][1] + bg1, c[f][j + 3][1] + bl1);
                    *reinterpret_cast<__half2*>(
                        g_ah + (size_t)(e * TOK + r0) * KDIM + gc) =
                        __floats2half2_rn(a0, a1);
                }
                if (r0 + 8 < ne) {
                    float a0 = swi(c[f][j][2] + bg0, c[f][j + 3][2] + bl0);
                    float a1 = swi(c[f][j][3] + bg1, c[f][j + 3][3] + bl1);
                    *reinterpret_cast<__half2*>(
                        g_ah + (size_t)(e * TOK + r0 + 8) * KDIM + gc) =
                        __floats2half2_rn(a0, a1);
                }
            }
        }
    } else {
        const float* be = bias + (size_t)e * HID;
#pragma unroll
        for (int f = 0; f < 4; f++) {
            int r0 = rbase + f * 16;
#pragma unroll
            for (int n = 0; n < 6; n++) {
                int gc = n0 + wn * 48 + n * 8 + (lane & 3) * 2;
                float bx = be[gc], by = be[gc + 1];
                if (r0 < ne) {
                    float2 v = make_float2(c[f][n][0] + bx, c[f][n][1] + by);
                    *reinterpret_cast<float2*>(
                        g_yp + (size_t)(e * TOK + r0) * HID + gc) = v;
                }
                if (r0 + 8 < ne) {
                    float2 v = make_float2(c[f][n][2] + bx, c[f][n][3] + by);
                    *reinterpret_cast<float2*>(
                        g_yp + (size_t)(e * TOK + r0 + 8) * HID + gc) = v;
                }
            }
        }
    }
}

// ---------------- weighted combine ----------------
__global__ void combine_kernel(float* __restrict__ y) {
    int idx = blockIdx.x * blockDim.x + threadIdx.x;
    const int per_row = HID / 4;
    if (idx >= TOK * per_row) return;
    int t = idx / per_row;
    int c = (idx - t * per_row) * 4;
    float4 accv = make_float4(0.f, 0.f, 0.f, 0.f);
#pragma unroll
    for (int k = 0; k < TOPK; k++) {
        int p = g_pos[t][k];
        float wv = g_w[t][k];
        float4 v = *reinterpret_cast<const float4*>(&g_yp[(size_t)p * HID + c]);
        accv.x += wv * v.x; accv.y += wv * v.y;
        accv.z += wv * v.z; accv.w += wv * v.w;
    }
    *reinterpret_cast<float4*>(&y[(size_t)t * HID + c]) = accv;
}

// ---------------- launch ----------------
extern "C" void kernel_launch(void* const* d_in, const int* in_sizes, int n_in,
                              void* d_out, int out_size) {
    const float* x  = (const float*)d_in[0];
    const float* gw = (const float*)d_in[1];
    const float* gb = (const float*)d_in[2];
    const float* w1 = (const float*)d_in[3];
    const float* b1 = (const float*)d_in[4];
    const float* w2 = (const float*)d_in[5];
    const float* b2 = (const float*)d_in[6];
    float* y = (float*)d_out;

    cudaFuncSetAttribute(mma_gemm_kernel<true>,
                         cudaFuncAttributeMaxDynamicSharedMemorySize, SMEM_GEMM);
    cudaFuncSetAttribute(mma_gemm_kernel<false>,
                         cudaFuncAttributeMaxDynamicSharedMemorySize, SMEM_GEMM);

    convert_x_kernel<<<(TOK * KDIM / 4 + 255) / 256, 256>>>(x);
    router_kernel<<<TOK / 8, 256>>>(x, gw, gb);
    convert_w_kernel<0><<<(int)(((size_t)NEXP * KDIM * N1 / 4 + 255) / 256), 256>>>(w1);
    convert_w_kernel<1><<<(int)(((size_t)NEXP * KDIM * HID / 4 + 255) / 256), 256>>>(w2);

    // m-blocks of 256: ceil(2048/256) = 8
    mma_gemm_kernel<true><<<dim3(8, 30, NEXP), 512, SMEM_GEMM>>>(b1);
    mma_gemm_kernel<false><<<dim3(8, 15, NEXP), 512, SMEM_GEMM>>>(b2);
    combine_kernel<<<(TOK * (HID / 4) + 255) / 256, 256>>>(y);
}

// round 14
// speedup vs baseline: 1.0929x; 1.0929x over previous
#include <cuda_runtime.h>
#include <cuda_fp16.h>
#include <cstdint>

#define TOK   2048
#define HID   2880
#define INTER 2880
#define NEXP  8
#define TOPK  4
#define N1    (2*INTER)        // 5760
#define MAXR  (NEXP*TOK)       // 16384
#define KDIM  2880

__device__ __constant__ float c_alpha = 1.702f;
__device__ __constant__ float c_limit = 7.0f;

// ---------------- static scratch ----------------
__device__ int   g_cnt[NEXP];
__device__ int   g_tok[NEXP][TOK];
__device__ int   g_pos[TOK][TOPK];
__device__ float g_w  [TOK][TOPK];
__device__ __align__(16) float  g_yp [(size_t)MAXR * HID];
__device__ __align__(16) __half g_xh [(size_t)TOK * KDIM];
__device__ __align__(16) __half g_ah [(size_t)MAXR * KDIM];

// ---------------- helpers ----------------
__device__ __forceinline__ uint32_t smem_to_u32(const void* p) {
    uint32_t a;
    asm("{ .reg .u64 t; cvta.to.shared.u64 t, %1; cvt.u32.u64 %0, t; }"
        : "=r"(a) : "l"(p));
    return a;
}
__device__ __forceinline__ void ldsm4(uint32_t* r, uint32_t addr) {
    asm volatile("ldmatrix.sync.aligned.m8n8.x4.shared.b16 {%0,%1,%2,%3}, [%4];"
                 : "=r"(r[0]), "=r"(r[1]), "=r"(r[2]), "=r"(r[3])
                 : "r"(addr) : "memory");
}
__device__ __forceinline__ void ldsm4t(uint32_t* r, uint32_t addr) {
    asm volatile("ldmatrix.sync.aligned.m8n8.x4.trans.shared.b16 {%0,%1,%2,%3}, [%4];"
                 : "=r"(r[0]), "=r"(r[1]), "=r"(r[2]), "=r"(r[3])
                 : "r"(addr) : "memory");
}
__device__ __forceinline__ void ldsm2t(uint32_t* r, uint32_t addr) {
    asm volatile("ldmatrix.sync.aligned.m8n8.x2.trans.shared.b16 {%0,%1}, [%2];"
                 : "=r"(r[0]), "=r"(r[1])
                 : "r"(addr) : "memory");
}
__device__ __forceinline__ void mma_f16(float* c, const uint32_t* a, const uint32_t* b) {
    asm volatile(
        "mma.sync.aligned.m16n8k16.row.col.f32.f16.f16.f32 "
        "{%0,%1,%2,%3}, {%4,%5,%6,%7}, {%8,%9}, {%0,%1,%2,%3};"
        : "+f"(c[0]), "+f"(c[1]), "+f"(c[2]), "+f"(c[3])
        : "r"(a[0]), "r"(a[1]), "r"(a[2]), "r"(a[3]), "r"(b[0]), "r"(b[1]));
}
__device__ __forceinline__ void cpa16(uint32_t dst, const void* src) {
    asm volatile("cp.async.cg.shared.global [%0], [%1], 16;"
                 :: "r"(dst), "l"(src) : "memory");
}
#define CP_COMMIT() asm volatile("cp.async.commit_group;" ::: "memory")
#define CP_WAIT0()  asm volatile("cp.async.wait_group 0;" ::: "memory")

union H4 { unsigned long long u; __half h[4]; };
union HU4 { uint4 u; __half2 h[4]; };

// ---------------- router ----------------
__global__ void router_kernel(const float* __restrict__ x,
                              const float* __restrict__ gw,
                              const float* __restrict__ gb) {
    int warp = threadIdx.x >> 5, lane = threadIdx.x & 31;
    int t = blockIdx.x * 8 + warp;
    if (t >= TOK) return;
    const float* xr = x + (size_t)t * HID;
    float acc[NEXP];
#pragma unroll
    for (int e = 0; e < NEXP; e++) acc[e] = 0.f;
    for (int h = lane; h < HID; h += 32) {
        float xv = xr[h];
        const float4* g4 = reinterpret_cast<const float4*>(gw + (size_t)h * NEXP);
        float4 ga = g4[0], gbv = g4[1];
        acc[0] += xv * ga.x;  acc[1] += xv * ga.y;
        acc[2] += xv * ga.z;  acc[3] += xv * ga.w;
        acc[4] += xv * gbv.x; acc[5] += xv * gbv.y;
        acc[6] += xv * gbv.z; acc[7] += xv * gbv.w;
    }
#pragma unroll
    for (int e = 0; e < NEXP; e++)
#pragma unroll
        for (int off = 16; off; off >>= 1)
            acc[e] += __shfl_xor_sync(0xffffffffu, acc[e], off);
    if (lane == 0) {
        float lg[NEXP];
#pragma unroll
        for (int e = 0; e < NEXP; e++) lg[e] = acc[e] + gb[e];
        int idx[TOPK]; float val[TOPK]; unsigned mask = 0;
#pragma unroll
        for (int k = 0; k < TOPK; k++) {
            float best = -3.4e38f; int bi = 0;
#pragma unroll
            for (int e = 0; e < NEXP; e++)
                if (!((mask >> e) & 1u) && lg[e] > best) { best = lg[e]; bi = e; }
            mask |= 1u << bi; idx[k] = bi; val[k] = best;
        }
        float m = val[0], s = 0.f, w[TOPK];
#pragma unroll
        for (int k = 0; k < TOPK; k++) { w[k] = expf(val[k] - m); s += w[k]; }
        float inv = 1.f / s;
#pragma unroll
        for (int k = 0; k < TOPK; k++) {
            int e = idx[k];
            int p = atomicAdd(&g_cnt[e], 1);
            g_tok[e][p] = t;
            g_pos[t][k] = e * TOK + p;
            g_w[t][k]   = w[k] * inv;
        }
    }
}

// ---------------- x -> fp16 (+ zero g_cnt in block 0) ----------------
__global__ void convert_x_kernel(const float* __restrict__ x) {
    if (blockIdx.x == 0 && threadIdx.x < NEXP) g_cnt[threadIdx.x] = 0;
    size_t i4 = (size_t)blockIdx.x * blockDim.x + threadIdx.x;
    if (i4 >= (size_t)TOK * KDIM / 4) return;
    float4 v = reinterpret_cast<const float4*>(x)[i4];
    H4 h;
    h.h[0] = __float2half_rn(v.x); h.h[1] = __float2half_rn(v.y);
    h.h[2] = __float2half_rn(v.z); h.h[3] = __float2half_rn(v.w);
    reinterpret_cast<unsigned long long*>(g_xh)[i4] = h.u;
}

// ---------------- clamped SwiGLU scalar ----------------
__device__ __forceinline__ float swi(float g, float l) {
    g = fminf(g, c_limit);
    l = fminf(fmaxf(l, -c_limit), c_limit);
    float s = 1.f / (1.f + expf(-c_alpha * g));
    return g * s * (l + 1.0f);
}

// ---------------- fused GEMM, 512 threads, B = fp32 gmem -> fp16 smem ------
// CTA tile 128m x 192n; warp grid 4m x 4n, warp tile 32m x 48n.
// FIRST: 96 glu + 96 lin cols; each warp owns 24 glu + matching 24 lin.
// A: fp16 via cp.async (2-stage). B: fp32 LDG reg-prefetch -> cvt -> STS.
#define KC      64
#define NCHUNK  (KDIM / KC)            // 45
#define ASTRIDE 144
#define BSTRIDE 400
#define OFF_B   18432
#define STAGE   (18432 + 25600)        // 44032
#define SMEM_GEMM (2 * STAGE + 512)    // 88576

template<bool FIRST>
__global__ __launch_bounds__(512, 1)
void mma_gemm_kernel(const float* __restrict__ Bw, const float* __restrict__ bias) {
    extern __shared__ __align__(1024) char smem[];
    int tid = threadIdx.x;
    int e = blockIdx.z;
    int ne = g_cnt[e];
    int m0 = blockIdx.x * 128;
    if (m0 >= ne) return;
    constexpr int NW = FIRST ? N1 : HID;     // B row width in gmem
    int n0 = blockIdx.y * (FIRST ? 96 : 192);

    const __half* Ah_ = FIRST ? g_xh : g_ah;

    int* rowid = reinterpret_cast<int*>(smem + 2 * STAGE);
    if (tid < 128) {
        int mi = m0 + tid; if (mi >= ne) mi = ne - 1;
        rowid[tid] = FIRST ? g_tok[e][mi] : (e * TOK + mi);
    }
    __syncthreads();

    uint32_t sb = smem_to_u32(smem);
    int r8  = tid >> 3;                // 0..63
    int seg = tid & 7;
    int ra[2];
    ra[0] = rowid[r8];
    ra[1] = rowid[r8 + 64];

    // B loader slots: 3 granules; id = tid + j*512; row = id/24, g = id%24
    int brow_[3], bcol_[3];
#pragma unroll
    for (int j = 0; j < 3; j++) {
        int id = tid + j * 512;
        int row = id / 24, g = id - row * 24;
        brow_[j] = row;
        bcol_[j] = FIRST ? ((g < 12) ? (n0 + g * 8) : (INTER + n0 + (g - 12) * 8))
                         : (n0 + g * 8);
    }
    const float* Be = Bw + (size_t)e * KDIM * NW;

    float4 pb[3][2];
    auto fetchB = [&](int chunk) {
        int kg0 = chunk * KC;
#pragma unroll
        for (int j = 0; j < 3; j++) {
            const float4* src = reinterpret_cast<const float4*>(
                Be + (size_t)(kg0 + brow_[j]) * NW + bcol_[j]);
            pb[j][0] = src[0];
            pb[j][1] = src[1];
        }
    };
    auto stsB = [&](int stg) {
        char* base = smem + stg * STAGE + OFF_B;
#pragma unroll
        for (int j = 0; j < 3; j++) {
            int id = tid + j * 512;
            int row = id / 24, g = id - row * 24;
            HU4 v;
            v.h[0] = __floats2half2_rn(pb[j][0].x, pb[j][0].y);
            v.h[1] = __floats2half2_rn(pb[j][0].z, pb[j][0].w);
            v.h[2] = __floats2half2_rn(pb[j][1].x, pb[j][1].y);
            v.h[3] = __floats2half2_rn(pb[j][1].z, pb[j][1].w);
            *reinterpret_cast<uint4*>(base + (uint32_t)row * BSTRIDE + g * 16) = v.u;
        }
    };
    auto loadA = [&](int stg, int chunk) {
        uint32_t sbase = sb + stg * STAGE;
        int kg0 = chunk * KC;
#pragma unroll
        for (int j = 0; j < 2; j++) {
            uint32_t so = (uint32_t)(r8 + 64 * j) * ASTRIDE + seg * 16;
            cpa16(sbase + so, Ah_ + (size_t)ra[j] * KDIM + kg0 + seg * 8);
        }
    };

    int w = tid >> 5, lane = tid & 31;
    int wn = w & 3, wm = w >> 2;               // 4 n-warps x 4 m-warps
    uint32_t row_add = (uint32_t)((lane & 7) + ((lane >> 3) & 1) * 8);
    uint32_t col16 = (uint32_t)(((lane >> 4) & 1) * 16);
    uint32_t bk_add = (uint32_t)((lane & 7) + ((lane >> 3) & 1) * 8);
    uint32_t bn8 = (uint32_t)((lane >> 4) * 8);

    float c[2][6][4];
#pragma unroll
    for (int f = 0; f < 2; f++)
#pragma unroll
        for (int n = 0; n < 6; n++)
#pragma unroll
            for (int k = 0; k < 4; k++) c[f][n][k] = 0.f;

    fetchB(0);
    loadA(0, 0);
    CP_COMMIT();

    for (int i = 0; i < NCHUNK; i++) {
        CP_WAIT0();            // A of chunk i landed
        stsB(i & 1);           // publish B of chunk i (regs -> smem)
        __syncthreads();       // stage i fully visible
        if (i + 1 < NCHUNK) {
            fetchB(i + 1);     // LDG prefetch B(i+1) into regs
            loadA((i + 1) & 1, i + 1);
            CP_COMMIT();
        }

        uint32_t st = sb + (i & 1) * STAGE;
#pragma unroll
        for (int s = 0; s < 4; s++) {
            uint32_t brow = st + OFF_B + (s * 16 + bk_add) * BSTRIDE;
            uint32_t bh[6][2];
            if (FIRST) {
                uint32_t t4[4], t2[2];
                ldsm4t(t4, brow + (uint32_t)(wn * 24) * 2 + bn8 * 2);
                bh[0][0] = t4[0]; bh[0][1] = t4[1];
                bh[1][0] = t4[2]; bh[1][1] = t4[3];
                ldsm2t(t2, brow + (uint32_t)(wn * 24 + 16) * 2);
                bh[2][0] = t2[0]; bh[2][1] = t2[1];
                ldsm4t(t4, brow + (uint32_t)(96 + wn * 24) * 2 + bn8 * 2);
                bh[3][0] = t4[0]; bh[3][1] = t4[1];
                bh[4][0] = t4[2]; bh[4][1] = t4[3];
                ldsm2t(t2, brow + (uint32_t)(96 + wn * 24 + 16) * 2);
                bh[5][0] = t2[0]; bh[5][1] = t2[1];
            } else {
#pragma unroll
                for (int q = 0; q < 3; q++) {
                    uint32_t t4[4];
                    ldsm4t(t4, brow + (uint32_t)(wn * 48 + q * 16) * 2 + bn8 * 2);
                    bh[2 * q][0] = t4[0];     bh[2 * q][1] = t4[1];
                    bh[2 * q + 1][0] = t4[2]; bh[2 * q + 1][1] = t4[3];
                }
            }
#pragma unroll
            for (int f = 0; f < 2; f++) {
                uint32_t rr = (uint32_t)(wm * 32 + f * 16) + row_add;
                uint32_t ah[4];
                ldsm4(ah, st + rr * ASTRIDE + (uint32_t)(s * 32) + col16);
#pragma unroll
                for (int n = 0; n < 6; n++)
                    mma_f16(c[f][n], ah, bh[n]);
            }
        }
        __syncthreads();       // all reads of stage i done before stsB overwrites
    }

    int rbase = m0 + wm * 32 + (lane >> 2);
    if (FIRST) {
        const float* be = bias + (size_t)e * N1;
#pragma unroll
        for (int f = 0; f < 2; f++) {
            int r0 = rbase + f * 16;
#pragma unroll
            for (int j = 0; j < 3; j++) {
                int gc = n0 + wn * 24 + j * 8 + (lane & 3) * 2;
                float bg0 = be[gc], bg1 = be[gc + 1];
                float bl0 = be[INTER + gc], bl1 = be[INTER + gc + 1];
                if (r0 < ne) {
                    float a0 = swi(c[f][j][0] + bg0, c[f][j + 3][0] + bl0);
                    float a1 = swi(c[f][j][1] + bg1, c[f][j + 3][1] + bl1);
                    *reinterpret_cast<__half2*>(
                        g_ah + (size_t)(e * TOK + r0) * KDIM + gc) =
                        __floats2half2_rn(a0, a1);
                }
                if (r0 + 8 < ne) {
                    float a0 = swi(c[f][j][2] + bg0, c[f][j + 3][2] + bl0);
                    float a1 = swi(c[f][j][3] + bg1, c[f][j + 3][3] + bl1);
                    *reinterpret_cast<__half2*>(
                        g_ah + (size_t)(e * TOK + r0 + 8) * KDIM + gc) =
                        __floats2half2_rn(a0, a1);
                }
            }
        }
    } else {
        const float* be = bias + (size_t)e * HID;
#pragma unroll
        for (int f = 0; f < 2; f++) {
            int r0 = rbase + f * 16;
#pragma unroll
            for (int n = 0; n < 6; n++) {
                int gc = n0 + wn * 48 + n * 8 + (lane & 3) * 2;
                float bx = be[gc], by = be[gc + 1];
                if (r0 < ne) {
                    float2 v = make_float2(c[f][n][0] + bx, c[f][n][1] + by);
                    *reinterpret_cast<float2*>(
                        g_yp + (size_t)(e * TOK + r0) * HID + gc) = v;
                }
                if (r0 + 8 < ne) {
                    float2 v = make_float2(c[f][n][2] + bx, c[f][n][3] + by);
                    *reinterpret_cast<float2*>(
                        g_yp + (size_t)(e * TOK + r0 + 8) * HID + gc) = v;
                }
            }
        }
    }
}

// ---------------- weighted combine ----------------
__global__ void combine_kernel(float* __restrict__ y) {
    int idx = blockIdx.x * blockDim.x + threadIdx.x;
    const int per_row = HID / 4;
    if (idx >= TOK * per_row) return;
    int t = idx / per_row;
    int c = (idx - t * per_row) * 4;
    float4 accv = make_float4(0.f, 0.f, 0.f, 0.f);
#pragma unroll
    for (int k = 0; k < TOPK; k++) {
        int p = g_pos[t][k];
        float wv = g_w[t][k];
        float4 v = *reinterpret_cast<const float4*>(&g_yp[(size_t)p * HID + c]);
        accv.x += wv * v.x; accv.y += wv * v.y;
        accv.z += wv * v.z; accv.w += wv * v.w;
    }
    *reinterpret_cast<float4*>(&y[(size_t)t * HID + c]) = accv;
}

// ---------------- launch ----------------
extern "C" void kernel_launch(void* const* d_in, const int* in_sizes, int n_in,
                              void* d_out, int out_size) {
    const float* x  = (const float*)d_in[0];
    const float* gw = (const float*)d_in[1];
    const float* gb = (const float*)d_in[2];
    const float* w1 = (const float*)d_in[3];
    const float* b1 = (const float*)d_in[4];
    const float* w2 = (const float*)d_in[5];
    const float* b2 = (const float*)d_in[6];
    float* y = (float*)d_out;

    cudaFuncSetAttribute(mma_gemm_kernel<true>,
                         cudaFuncAttributeMaxDynamicSharedMemorySize, SMEM_GEMM);
    cudaFuncSetAttribute(mma_gemm_kernel<false>,
                         cudaFuncAttributeMaxDynamicSharedMemorySize, SMEM_GEMM);

    convert_x_kernel<<<(TOK * KDIM / 4 + 255) / 256, 256>>>(x);
    router_kernel<<<TOK / 8, 256>>>(x, gw, gb);

    mma_gemm_kernel<true><<<dim3(16, 30, NEXP), 512, SMEM_GEMM>>>(w1, b1);
    mma_gemm_kernel<false><<<dim3(16, 15, NEXP), 512, SMEM_GEMM>>>(w2, b2);
    combine_kernel<<<(TOK * (HID / 4) + 255) / 256, 256>>>(y);
}

// round 15
// speedup vs baseline: 1.1379x; 1.0412x over previous
#include <cuda_runtime.h>
#include <cuda_fp16.h>
#include <cstdint>

#define TOK   2048
#define HID   2880
#define INTER 2880
#define NEXP  8
#define TOPK  4
#define N1    (2*INTER)        // 5760
#define MAXR  (NEXP*TOK)       // 16384
#define KDIM  2880

__device__ __constant__ float c_alpha = 1.702f;
__device__ __constant__ float c_limit = 7.0f;

// ---------------- static scratch ----------------
__device__ int   g_cnt[NEXP];
__device__ int   g_tok[NEXP][TOK];
__device__ int   g_pos[TOK][TOPK];
__device__ float g_w  [TOK][TOPK];
__device__ __align__(16) float  g_yp [(size_t)MAXR * HID];
__device__ __align__(16) __half g_xh [(size_t)TOK * KDIM];
__device__ __align__(16) __half g_w1h[(size_t)NEXP * KDIM * N1];   // [e][k][n]
__device__ __align__(16) __half g_w2h[(size_t)NEXP * KDIM * HID];  // [e][k][n]
__device__ __align__(16) __half g_ah [(size_t)MAXR * KDIM];

// ---------------- helpers ----------------
__device__ __forceinline__ uint32_t smem_to_u32(const void* p) {
    uint32_t a;
    asm("{ .reg .u64 t; cvta.to.shared.u64 t, %1; cvt.u32.u64 %0, t; }"
        : "=r"(a) : "l"(p));
    return a;
}
__device__ __forceinline__ void ldsm4(uint32_t* r, uint32_t addr) {
    asm volatile("ldmatrix.sync.aligned.m8n8.x4.shared.b16 {%0,%1,%2,%3}, [%4];"
                 : "=r"(r[0]), "=r"(r[1]), "=r"(r[2]), "=r"(r[3])
                 : "r"(addr) : "memory");
}
__device__ __forceinline__ void ldsm4t(uint32_t* r, uint32_t addr) {
    asm volatile("ldmatrix.sync.aligned.m8n8.x4.trans.shared.b16 {%0,%1,%2,%3}, [%4];"
                 : "=r"(r[0]), "=r"(r[1]), "=r"(r[2]), "=r"(r[3])
                 : "r"(addr) : "memory");
}
__device__ __forceinline__ void ldsm2t(uint32_t* r, uint32_t addr) {
    asm volatile("ldmatrix.sync.aligned.m8n8.x2.trans.shared.b16 {%0,%1}, [%2];"
                 : "=r"(r[0]), "=r"(r[1])
                 : "r"(addr) : "memory");
}
__device__ __forceinline__ void mma_f16(float* c, const uint32_t* a, const uint32_t* b) {
    asm volatile(
        "mma.sync.aligned.m16n8k16.row.col.f32.f16.f16.f32 "
        "{%0,%1,%2,%3}, {%4,%5,%6,%7}, {%8,%9}, {%0,%1,%2,%3};"
        : "+f"(c[0]), "+f"(c[1]), "+f"(c[2]), "+f"(c[3])
        : "r"(a[0]), "r"(a[1]), "r"(a[2]), "r"(a[3]), "r"(b[0]), "r"(b[1]));
}
__device__ __forceinline__ void cpa16(uint32_t dst, const void* src) {
    asm volatile("cp.async.cg.shared.global [%0], [%1], 16;"
                 :: "r"(dst), "l"(src) : "memory");
}
#define CP_COMMIT() asm volatile("cp.async.commit_group;" ::: "memory")
#define CP_WAIT0()  asm volatile("cp.async.wait_group 0;" ::: "memory")

union H4 { unsigned long long u; __half h[4]; };

// ---------------- router ----------------
__global__ void router_kernel(const float* __restrict__ x,
                              const float* __restrict__ gw,
                              const float* __restrict__ gb) {
    int warp = threadIdx.x >> 5, lane = threadIdx.x & 31;
    int t = blockIdx.x * 8 + warp;
    if (t >= TOK) return;
    const float* xr = x + (size_t)t * HID;
    float acc[NEXP];
#pragma unroll
    for (int e = 0; e < NEXP; e++) acc[e] = 0.f;
    for (int h = lane; h < HID; h += 32) {
        float xv = xr[h];
        const float4* g4 = reinterpret_cast<const float4*>(gw + (size_t)h * NEXP);
        float4 ga = g4[0], gbv = g4[1];
        acc[0] += xv * ga.x;  acc[1] += xv * ga.y;
        acc[2] += xv * ga.z;  acc[3] += xv * ga.w;
        acc[4] += xv * gbv.x; acc[5] += xv * gbv.y;
        acc[6] += xv * gbv.z; acc[7] += xv * gbv.w;
    }
#pragma unroll
    for (int e = 0; e < NEXP; e++)
#pragma unroll
        for (int off = 16; off; off >>= 1)
            acc[e] += __shfl_xor_sync(0xffffffffu, acc[e], off);
    if (lane == 0) {
        float lg[NEXP];
#pragma unroll
        for (int e = 0; e < NEXP; e++) lg[e] = acc[e] + gb[e];
        int idx[TOPK]; float val[TOPK]; unsigned mask = 0;
#pragma unroll
        for (int k = 0; k < TOPK; k++) {
            float best = -3.4e38f; int bi = 0;
#pragma unroll
            for (int e = 0; e < NEXP; e++)
                if (!((mask >> e) & 1u) && lg[e] > best) { best = lg[e]; bi = e; }
            mask |= 1u << bi; idx[k] = bi; val[k] = best;
        }
        float m = val[0], s = 0.f, w[TOPK];
#pragma unroll
        for (int k = 0; k < TOPK; k++) { w[k] = expf(val[k] - m); s += w[k]; }
        float inv = 1.f / s;
#pragma unroll
        for (int k = 0; k < TOPK; k++) {
            int e = idx[k];
            int p = atomicAdd(&g_cnt[e], 1);
            g_tok[e][p] = t;
            g_pos[t][k] = e * TOK + p;
            g_w[t][k]   = w[k] * inv;
        }
    }
}

// ---------------- x -> fp16 (+ zero g_cnt in block 0) ----------------
__global__ void convert_x_kernel(const float* __restrict__ x) {
    if (blockIdx.x == 0 && threadIdx.x < NEXP) g_cnt[threadIdx.x] = 0;
    size_t i4 = (size_t)blockIdx.x * blockDim.x + threadIdx.x;
    if (i4 >= (size_t)TOK * KDIM / 4) return;
    float4 v = reinterpret_cast<const float4*>(x)[i4];
    H4 h;
    h.h[0] = __float2half_rn(v.x); h.h[1] = __float2half_rn(v.y);
    h.h[2] = __float2half_rn(v.z); h.h[3] = __float2half_rn(v.w);
    reinterpret_cast<unsigned long long*>(g_xh)[i4] = h.u;
}

// ---------------- weights -> fp16, layout preserved [e][k][n] ----------------
template<int WHICH>
__global__ void convert_w_kernel(const float* __restrict__ W) {
    __half* TH = WHICH ? g_w2h : g_w1h;   // device-code symbol ref
    const size_t n4 = ((size_t)NEXP * KDIM * (WHICH ? HID : N1)) / 4;
    size_t i4 = (size_t)blockIdx.x * blockDim.x + threadIdx.x;
    if (i4 >= n4) return;
    float4 v = reinterpret_cast<const float4*>(W)[i4];
    H4 h;
    h.h[0] = __float2half_rn(v.x); h.h[1] = __float2half_rn(v.y);
    h.h[2] = __float2half_rn(v.z); h.h[3] = __float2half_rn(v.w);
    reinterpret_cast<unsigned long long*>(TH)[i4] = h.u;
}

// ---------------- clamped SwiGLU scalar ----------------
__device__ __forceinline__ float swi(float g, float l) {
    g = fminf(g, c_limit);
    l = fminf(fmaxf(l, -c_limit), c_limit);
    float s = 1.f / (1.f + expf(-c_alpha * g));
    return g * s * (l + 1.0f);
}

// ---------------- fused GEMM: CTA 192m x 192n, 384 threads -----------------
// Warp grid 3m x 4n, warp tile 64m x 48n (f=4, n=6).
// FIRST: 96 glu + 96 lin cols; each warp owns 24 glu + matching 24 lin.
// SMEM: A [192][144B], B [64 k-rows][400B]; 2-stage cp.async.
#define KC      64
#define NCHUNK  (KDIM / KC)            // 45
#define ASTRIDE 144
#define BSTRIDE 400
#define OFF_B   27648
#define STAGE   (27648 + 25600)        // 53248
#define SMEM_GEMM (2 * STAGE + 1024)   // 107520

template<bool FIRST>
__global__ __launch_bounds__(384, 1)
void mma_gemm_kernel(const float* __restrict__ bias) {
    extern __shared__ __align__(1024) char smem[];
    int tid = threadIdx.x;
    int e = blockIdx.z;
    int ne = g_cnt[e];
    int m0 = blockIdx.x * 192;
    if (m0 >= ne) return;
    constexpr int NW = FIRST ? N1 : HID;     // B row width in gmem
    int n0 = blockIdx.y * (FIRST ? 96 : 192);

    const __half* Ah_ = FIRST ? g_xh : g_ah;
    const __half* Bh_ = FIRST ? g_w1h : g_w2h;

    int* rowid = reinterpret_cast<int*>(smem + 2 * STAGE);
    if (tid < 192) {
        int mi = m0 + tid; if (mi >= ne) mi = ne - 1;
        rowid[tid] = FIRST ? g_tok[e][mi] : (e * TOK + mi);
    }
    __syncthreads();

    uint32_t sb = smem_to_u32(smem);
    // A loader: slots id = tid + j*384 (j=0..3): row = r8 + 48j, seg const
    int r8  = tid >> 3;                // 0..47
    int seg = tid & 7;
    int ra[4];
#pragma unroll
    for (int j = 0; j < 4; j++) ra[j] = rowid[r8 + 48 * j];
    // B loader: slots id = tid + j*384: row = br + 16j, granule bg const
    int br = tid / 24;                 // 0..15
    int bg = tid - br * 24;            // 0..23
    int bcol = FIRST ? ((bg < 12) ? (n0 + bg * 8) : (INTER + n0 + (bg - 12) * 8))
                     : (n0 + bg * 8);
    const __half* Be = Bh_ + (size_t)e * KDIM * NW;

    auto load_stage = [&](int stg, int chunk) {
        uint32_t sbase = sb + stg * STAGE;
        int kg0 = chunk * KC;
#pragma unroll
        for (int j = 0; j < 4; j++) {
            uint32_t so = (uint32_t)(r8 + 48 * j) * ASTRIDE + seg * 16;
            cpa16(sbase + so, Ah_ + (size_t)ra[j] * KDIM + kg0 + seg * 8);
        }
#pragma unroll
        for (int j = 0; j < 4; j++) {
            int row = br + 16 * j;
            cpa16(sbase + OFF_B + (uint32_t)row * BSTRIDE + bg * 16,
                  Be + (size_t)(kg0 + row) * NW + bcol);
        }
    };

    int w = tid >> 5, lane = tid & 31;
    int wn = w & 3, wm = w >> 2;               // 4 n-warps x 3 m-warps
    uint32_t row_add = (uint32_t)((lane & 7) + ((lane >> 3) & 1) * 8);
    uint32_t col16 = (uint32_t)(((lane >> 4) & 1) * 16);
    uint32_t bk_add = (uint32_t)((lane & 7) + ((lane >> 3) & 1) * 8);
    uint32_t bn8 = (uint32_t)((lane >> 4) * 8);

    float c[4][6][4];
#pragma unroll
    for (int f = 0; f < 4; f++)
#pragma unroll
        for (int n = 0; n < 6; n++)
#pragma unroll
            for (int k = 0; k < 4; k++) c[f][n][k] = 0.f;

    load_stage(0, 0);
    CP_COMMIT();

    for (int i = 0; i < NCHUNK; i++) {
        CP_WAIT0();
        __syncthreads();
        if (i + 1 < NCHUNK) { load_stage((i + 1) & 1, i + 1); CP_COMMIT(); }

        uint32_t st = sb + (i & 1) * STAGE;
#pragma unroll
        for (int s = 0; s < 4; s++) {
            uint32_t brow = st + OFF_B + (s * 16 + bk_add) * BSTRIDE;
            uint32_t bh[6][2];
            if (FIRST) {
                uint32_t t4[4], t2[2];
                ldsm4t(t4, brow + (uint32_t)(wn * 24) * 2 + bn8 * 2);
                bh[0][0] = t4[0]; bh[0][1] = t4[1];
                bh[1][0] = t4[2]; bh[1][1] = t4[3];
                ldsm2t(t2, brow + (uint32_t)(wn * 24 + 16) * 2);
                bh[2][0] = t2[0]; bh[2][1] = t2[1];
                ldsm4t(t4, brow + (uint32_t)(96 + wn * 24) * 2 + bn8 * 2);
                bh[3][0] = t4[0]; bh[3][1] = t4[1];
                bh[4][0] = t4[2]; bh[4][1] = t4[3];
                ldsm2t(t2, brow + (uint32_t)(96 + wn * 24 + 16) * 2);
                bh[5][0] = t2[0]; bh[5][1] = t2[1];
            } else {
#pragma unroll
                for (int q = 0; q < 3; q++) {
                    uint32_t t4[4];
                    ldsm4t(t4, brow + (uint32_t)(wn * 48 + q * 16) * 2 + bn8 * 2);
                    bh[2 * q][0] = t4[0];     bh[2 * q][1] = t4[1];
                    bh[2 * q + 1][0] = t4[2]; bh[2 * q + 1][1] = t4[3];
                }
            }
#pragma unroll
            for (int f = 0; f < 4; f++) {
                uint32_t rr = (uint32_t)(wm * 64 + f * 16) + row_add;
                uint32_t ah[4];
                ldsm4(ah, st + rr * ASTRIDE + (uint32_t)(s * 32) + col16);
#pragma unroll
                for (int n = 0; n < 6; n++)
                    mma_f16(c[f][n], ah, bh[n]);
            }
        }
        __syncthreads();
    }

    int rbase = m0 + wm * 64 + (lane >> 2);
    if (FIRST) {
        const float* be = bias + (size_t)e * N1;
#pragma unroll
        for (int f = 0; f < 4; f++) {
            int r0 = rbase + f * 16;
#pragma unroll
            for (int j = 0; j < 3; j++) {
                int gc = n0 + wn * 24 + j * 8 + (lane & 3) * 2;
                float bg0 = be[gc], bg1 = be[gc + 1];
                float bl0 = be[INTER + gc], bl1 = be[INTER + gc + 1];
                if (r0 < ne) {
                    float a0 = swi(c[f][j][0] + bg0, c[f][j + 3][0] + bl0);
                    float a1 = swi(c[f][j][1] + bg1, c[f][j + 3][1] + bl1);
                    *reinterpret_cast<__half2*>(
                        g_ah + (size_t)(e * TOK + r0) * KDIM + gc) =
                        __floats2half2_rn(a0, a1);
                }
                if (r0 + 8 < ne) {
                    float a0 = swi(c[f][j][2] + bg0, c[f][j + 3][2] + bl0);
                    float a1 = swi(c[f][j][3] + bg1, c[f][j + 3][3] + bl1);
                    *reinterpret_cast<__half2*>(
                        g_ah + (size_t)(e * TOK + r0 + 8) * KDIM + gc) =
                        __floats2half2_rn(a0, a1);
                }
            }
        }
    } else {
        const float* be = bias + (size_t)e * HID;
#pragma unroll
        for (int f = 0; f < 4; f++) {
            int r0 = rbase + f * 16;
#pragma unroll
            for (int n = 0; n < 6; n++) {
                int gc = n0 + wn * 48 + n * 8 + (lane & 3) * 2;
                float bx = be[gc], by = be[gc + 1];
                if (r0 < ne) {
                    float2 v = make_float2(c[f][n][0] + bx, c[f][n][1] + by);
                    *reinterpret_cast<float2*>(
                        g_yp + (size_t)(e * TOK + r0) * HID + gc) = v;
                }
                if (r0 + 8 < ne) {
                    float2 v = make_float2(c[f][n][2] + bx, c[f][n][3] + by);
                    *reinterpret_cast<float2*>(
                        g_yp + (size_t)(e * TOK + r0 + 8) * HID + gc) = v;
                }
            }
        }
    }
}

// ---------------- weighted combine ----------------
__global__ void combine_kernel(float* __restrict__ y) {
    int idx = blockIdx.x * blockDim.x + threadIdx.x;
    const int per_row = HID / 4;
    if (idx >= TOK * per_row) return;
    int t = idx / per_row;
    int c = (idx - t * per_row) * 4;
    float4 accv = make_float4(0.f, 0.f, 0.f, 0.f);
#pragma unroll
    for (int k = 0; k < TOPK; k++) {
        int p = g_pos[t][k];
        float wv = g_w[t][k];
        float4 v = *reinterpret_cast<const float4*>(&g_yp[(size_t)p * HID + c]);
        accv.x += wv * v.x; accv.y += wv * v.y;
        accv.z += wv * v.z; accv.w += wv * v.w;
    }
    *reinterpret_cast<float4*>(&y[(size_t)t * HID + c]) = accv;
}

// ---------------- launch ----------------
extern "C" void kernel_launch(void* const* d_in, const int* in_sizes, int n_in,
                              void* d_out, int out_size) {
    const float* x  = (const float*)d_in[0];
    const float* gw = (const float*)d_in[1];
    const float* gb = (const float*)d_in[2];
    const float* w1 = (const float*)d_in[3];
    const float* b1 = (const float*)d_in[4];
    const float* w2 = (const float*)d_in[5];
    const float* b2 = (const float*)d_in[6];
    float* y = (float*)d_out;

    cudaFuncSetAttribute(mma_gemm_kernel<true>,
                         cudaFuncAttributeMaxDynamicSharedMemorySize, SMEM_GEMM);
    cudaFuncSetAttribute(mma_gemm_kernel<false>,
                         cudaFuncAttributeMaxDynamicSharedMemorySize, SMEM_GEMM);

    convert_x_kernel<<<(TOK * KDIM / 4 + 255) / 256, 256>>>(x);
    router_kernel<<<TOK / 8, 256>>>(x, gw, gb);
    convert_w_kernel<0><<<(int)(((size_t)NEXP * KDIM * N1 / 4 + 255) / 256), 256>>>(w1);
    convert_w_kernel<1><<<(int)(((size_t)NEXP * KDIM * HID / 4 + 255) / 256), 256>>>(w2);

    // m-blocks: ceil(2048/192) = 11
    mma_gemm_kernel<true><<<dim3(11, 30, NEXP), 384, SMEM_GEMM>>>(b1);
    mma_gemm_kernel<false><<<dim3(11, 15, NEXP), 384, SMEM_GEMM>>>(b2);
    combine_kernel<<<(TOK * (HID / 4) + 255) / 256, 256>>>(y);
}